// round 16
// baseline (speedup 1.0000x reference)
#include <cuda_runtime.h>
#include <math.h>
#include <stdint.h>

// Problem constants: B=2, S=4096, H=1024, NH=16, hd=64
#define BATCH 2
#define SEQ   4096
#define HID   1024
#define NHEAD 16
#define HDIM  64
#define TOKENS (BATCH*SEQ)          // 8192
#define QKVW  (3*HID)               // 3072

// ---------------- device scratch ----------------
__device__ float g_qkv  [(size_t)TOKENS * QKVW];  // QKV gemm output, normal [t][3H]
__device__ float g_apk  [(size_t)TOKENS * HID];   // hidden, packed (A fragment order)
__device__ float g_q    [(size_t)TOKENS * HID];   // [bh][s][hd] normal, tf32-rounded
__device__ float g_kpk  [(size_t)TOKENS * HID];   // K packed for flash tiles
__device__ float g_vpk  [(size_t)TOKENS * HID];   // V packed for flash tiles ([hd][kv])
__device__ float g_opk  [(size_t)TOKENS * HID];   // attn out, packed (A fragment order)
__device__ float g_wqkv_pk[(size_t)QKVW * HID];   // W_qkv^T packed (B fragment order)
__device__ float g_wo_pk  [(size_t)HID * HID];    // W_o^T packed (B fragment order)

// ---------------- tf32 / layout helpers ----------------
__device__ __forceinline__ unsigned f2tf(float f) {
    unsigned u; asm("cvt.rna.tf32.f32 %0, %1;" : "=r"(u) : "f"(f)); return u;
}
__device__ __forceinline__ float rtf(float f) { return __uint_as_float(f2tf(f)); }

__device__ __forceinline__ void mma8(float (&c)[4],
                                     unsigned a0, unsigned a1, unsigned a2, unsigned a3,
                                     unsigned b0, unsigned b1) {
    asm volatile(
        "mma.sync.aligned.m16n8k8.row.col.f32.tf32.tf32.f32 "
        "{%0,%1,%2,%3},{%4,%5,%6,%7},{%8,%9},{%0,%1,%2,%3};\n"
        : "+f"(c[0]), "+f"(c[1]), "+f"(c[2]), "+f"(c[3])
        : "r"(a0), "r"(a1), "r"(a2), "r"(a3), "r"(b0), "r"(b1));
}

__device__ __forceinline__ unsigned smem_u32(const void* p) {
    unsigned a;
    asm("{ .reg .u64 t; cvta.to.shared.u64 t, %1; cvt.u32.u64 %0, t; }" : "=r"(a) : "l"(p));
    return a;
}
__device__ __forceinline__ void cp16(unsigned dst, const void* src) {
    asm volatile("cp.async.cg.shared.global [%0], [%1], 16;\n" :: "r"(dst), "l"(src) : "memory");
}
#define CP_COMMIT() asm volatile("cp.async.commit_group;\n" ::: "memory")
#define CP_WAIT(n)  asm volatile("cp.async.wait_group %0;\n" :: "n"(n) : "memory")

// k-permutation within 8-groups (flash tiles): (c, c+4) adjacent -> LDS.64
__device__ __forceinline__ int pk8(int k) {
    return (k & ~7) | ((k & 3) << 1) | ((k >> 2) & 1);
}
// 64-float row xor swizzle (flash tiles)
__device__ __forceinline__ int swp64(int row, int p) {
    return row * 64 + ((((p >> 3) ^ (row & 7)) << 3) | (p & 7));
}

// ---- GEMM fragment-order offsets within a (128 rows x 32 k) = 4096-word tile ----
__device__ __forceinline__ int afrag_off(int r, int k) {   // r in [0,128), k in [0,32)
    int half = r >> 6, mt = (r >> 4) & 3, g = r & 7, hi = (r >> 3) & 1;
    int s = k >> 3, c2 = k & 3, h2 = (k >> 2) & 1;
    return ((half * 4 + mt) * 4 + s) * 128 + (g * 4 + c2) * 4 + h2 * 2 + hi;
}
__device__ __forceinline__ int bfrag_off(int n, int k) {   // n in [0,128), k in [0,32)
    int wq = n >> 5, nt = (n >> 3) & 3, g = n & 7;
    int s = k >> 3, c2 = k & 3, h2 = (k >> 2) & 1;
    return wq * 1024 + (nt * 4 + s) * 64 + (g * 4 + c2) * 2 + h2;
}

// ---------------- prep kernels ----------------
__global__ void pack_a(const float* __restrict__ src, float* __restrict__ dst, int K) {
    int i = blockIdx.x * blockDim.x + threadIdx.x;
    int kq = K >> 2;
    int row = i / kq, k = (i - row * kq) * 4;
    float4 v = ((const float4*)src)[i];
    float* d = dst + ((size_t)(row >> 7) * (K >> 5) + (k >> 5)) * 4096;
    int r = row & 127, kc = k & 31;
    float vv[4] = {v.x, v.y, v.z, v.w};
#pragma unroll
    for (int e = 0; e < 4; e++)
        d[afrag_off(r, kc + e)] = rtf(vv[e]);
}

__global__ void pack_wT(const float* __restrict__ src, float* __restrict__ dst,
                        int K, int N) {
    __shared__ float t[32][33];
    int bn = blockIdx.x * 32, bk = blockIdx.y * 32;
    int x = threadIdx.x, y = threadIdx.y;
#pragma unroll
    for (int i = 0; i < 32; i += 8)
        t[y + i][x] = src[(size_t)(bk + y + i) * N + bn + x];
    __syncthreads();
#pragma unroll
    for (int i = 0; i < 32; i += 8) {
        int n = bn + y + i, k = bk + x;
        size_t blk = ((size_t)(n >> 7) * (K >> 5) + (k >> 5)) * 4096;
        dst[blk + bfrag_off(n & 127, k & 31)] = rtf(t[x][y + i]);
    }
}

__global__ void pack_v(const float* __restrict__ qkv, float* __restrict__ v) {
    __shared__ float t[32][33];
    int bh = blockIdx.z, b = bh >> 4, h = bh & 15;
    const float* src = qkv + (size_t)b * SEQ * QKVW + 2 * HID + h * HDIM;
    int bx = blockIdx.x * 32;   // hd tile
    int by = blockIdx.y * 32;   // s tile
    int x = threadIdx.x, y = threadIdx.y;
#pragma unroll
    for (int i = 0; i < 32; i += 8)
        t[y + i][x] = src[(size_t)(by + y + i) * QKVW + bx + x];
    __syncthreads();
#pragma unroll
    for (int i = 0; i < 32; i += 8) {
        int hd = bx + y + i, s = by + x;
        size_t blk = ((size_t)bh * (SEQ >> 6) + (s >> 6)) * 4096;
        v[blk + swp64(hd, pk8(s & 63))] = rtf(t[x][y + i]);
    }
}

// ---------------- RMSNorm + RoPE: q normal, k packed for flash ----------------
__global__ void rmsnorm_rope_kernel(const float* __restrict__ qkv,
                                    const float* __restrict__ cosb,
                                    const float* __restrict__ sinb,
                                    const float* __restrict__ gq,
                                    const float* __restrict__ gk,
                                    float* __restrict__ qout,
                                    float* __restrict__ kout)
{
    int warp = (blockIdx.x * blockDim.x + threadIdx.x) >> 5;
    int lane = threadIdx.x & 31;
    if (warp >= TOKENS * NHEAD) return;
    int t = warp / NHEAD, h = warp % NHEAD;
    int s = t & (SEQ - 1), b = t / SEQ;
    int bh = b * NHEAD + h;

    const float* qp = qkv + (size_t)t * QKVW + h * HDIM;
    const float* kp = qp + HID;

    float q0 = qp[lane], q1 = qp[lane + 32];
    float k0 = kp[lane], k1 = kp[lane + 32];

    float sq = q0 * q0 + q1 * q1;
    float sk = k0 * k0 + k1 * k1;
#pragma unroll
    for (int off = 16; off; off >>= 1) {
        sq += __shfl_xor_sync(0xffffffffu, sq, off);
        sk += __shfl_xor_sync(0xffffffffu, sk, off);
    }
    float rq = rsqrtf(sq * (1.0f / HDIM) + 1e-6f);
    float rk = rsqrtf(sk * (1.0f / HDIM) + 1e-6f);
    q0 *= rq * gq[lane];  q1 *= rq * gq[lane + 32];
    k0 *= rk * gk[lane];  k1 *= rk * gk[lane + 32];

    float c0 = cosb[(size_t)s * HDIM + lane];
    float c1 = cosb[(size_t)s * HDIM + lane + 32];
    float s0 = sinb[(size_t)s * HDIM + lane];
    float s1 = sinb[(size_t)s * HDIM + lane + 32];

    size_t qb = ((size_t)bh * SEQ + s) * HDIM;
    qout[qb + lane]      = rtf(q0 * c0 - q1 * s0);
    qout[qb + lane + 32] = rtf(q1 * c1 + q0 * s1);

    size_t kblk = ((size_t)bh * (SEQ >> 6) + (s >> 6)) * 4096;
    int r = s & 63;
    kout[kblk + swp64(r, pk8(lane))]      = rtf(k0 * c0 - k1 * s0);
    kout[kblk + swp64(r, pk8(lane + 32))] = rtf(k1 * c1 + k0 * s1);
}

// ============ tf32 HMMA GEMM, fragment-order operands: C = A @ B^T, 128x128x32 ============
#define GS 3
#define STW 8192   // words per stage (A 4096 + B 4096)
__global__ __launch_bounds__(256, 2)
void gemm_mma(const float* __restrict__ Apk, const float* __restrict__ Bpk,
              float* __restrict__ C, int M, int N, int K)
{
    extern __shared__ float smf[];
    const int tid = threadIdx.x, lane = tid & 31, wid = tid >> 5;
    const int g = lane >> 2, c = lane & 3;
    const int half = wid >> 2, wq = wid & 3;
    const size_t bm = (size_t)blockIdx.y * 128, bn = (size_t)blockIdx.x * 128;
    const int NK = K >> 5;
    const float* ag = Apk + (size_t)blockIdx.y * NK * 4096;
    const float* bg = Bpk + (size_t)blockIdx.x * NK * 4096;
    const unsigned sb = smem_u32(smf);

    auto issue = [&](int kt, int st) {
        const float* a = ag + (size_t)kt * 4096;
        const float* b = bg + (size_t)kt * 4096;
        const unsigned d = sb + st * (STW * 4);
#pragma unroll
        for (int j = 0; j < 4; j++) {
            int ci = tid + 256 * j;
            cp16(d + ci * 16, a + ci * 4);
            cp16(d + 16384 + ci * 16, b + ci * 4);
        }
    };

    float acc[4][4][4];
#pragma unroll
    for (int i = 0; i < 4; i++)
#pragma unroll
        for (int j = 0; j < 4; j++)
#pragma unroll
            for (int r = 0; r < 4; r++) acc[i][j][r] = 0.f;

    issue(0, 0); CP_COMMIT();
    issue(1, 1); CP_COMMIT();

    for (int kt = 0; kt < NK; kt++) {
        CP_WAIT(1);
        __syncthreads();
        if (kt + 2 < NK) issue(kt + 2, (kt + 2) % 3);
        CP_COMMIT();

        const float* as = smf + (kt % 3) * STW + half * 2048 + lane * 4;
        const float* bs = smf + (kt % 3) * STW + 4096 + wq * 1024 + lane * 2;
#pragma unroll
        for (int s = 0; s < 4; s++) {
            uint4 a4[4];
            uint2 bv[4];
#pragma unroll
            for (int mt = 0; mt < 4; mt++)
                a4[mt] = *(const uint4*)&as[(mt * 4 + s) * 128];
#pragma unroll
            for (int nt = 0; nt < 4; nt++)
                bv[nt] = *(const uint2*)&bs[(nt * 4 + s) * 64];
#pragma unroll
            for (int mt = 0; mt < 4; mt++)
#pragma unroll
                for (int nt = 0; nt < 4; nt++)
                    mma8(acc[mt][nt], a4[mt].x, a4[mt].y, a4[mt].z, a4[mt].w,
                         bv[nt].x, bv[nt].y);
        }
    }

    const int wm = half * 64, wn = wq * 32;
#pragma unroll
    for (int mt = 0; mt < 4; mt++) {
        size_t row = bm + wm + mt * 16 + g;
#pragma unroll
        for (int nt = 0; nt < 4; nt++) {
            size_t col = bn + wn + nt * 8 + 2 * c;
            *(float2*)(C + row * N + col)       = make_float2(acc[mt][nt][0], acc[mt][nt][1]);
            *(float2*)(C + (row + 8) * N + col) = make_float2(acc[mt][nt][2], acc[mt][nt][3]);
        }
    }
}

// ---------------- causal flash attention: P via quad-shuffle, 3-stage cp.async ----------------
// P never touches smem: PV A-fragments are rebuilt from sacc with 2 quad-shuffles + select.
// smem: K 3x16KB + V 3x16KB = 96KB; 2 CTAs/SM = 192KB.
__global__ __launch_bounds__(256, 2)
void flash_mma(const float* __restrict__ Q, const float* __restrict__ Kpk,
               const float* __restrict__ Vpk, float* __restrict__ Opk)
{
    extern __shared__ float sm[];
    float* Ksm = sm;             // [3][64*64]
    float* Vsm = sm + 12288;     // [3][64*64]

    const int tid = threadIdx.x, lane = tid & 31, wid = tid >> 5;
    const int g = lane >> 2, c = lane & 3;
    const int qb = (SEQ / 128 - 1) - blockIdx.y;   // LPT: largest work first
    const int bh = blockIdx.x;
    const int b = bh >> 4, h = bh & 15;

    const float* Qg = Q + ((size_t)bh * SEQ + qb * 128) * HDIM;
    const float* Kg = Kpk + (size_t)bh * (SEQ >> 6) * 4096;
    const float* Vg = Vpk + (size_t)bh * (SEQ >> 6) * 4096;
    const unsigned ksb = smem_u32(Ksm), vsb = smem_u32(Vsm);

    // persistent Q fragments, pre-scaled by log2(e)/8
    const float QS = 0.18033688f;
    unsigned qf[8][4];
    {
        const float* q0 = Qg + (size_t)(wid * 16 + g) * HDIM;
        const float* q1 = q0 + 8 * HDIM;
#pragma unroll
        for (int s = 0; s < 8; s++) {
            qf[s][0] = f2tf(QS * __ldg(q0 + s * 8 + c));
            qf[s][1] = f2tf(QS * __ldg(q1 + s * 8 + c));
            qf[s][2] = f2tf(QS * __ldg(q0 + s * 8 + c + 4));
            qf[s][3] = f2tf(QS * __ldg(q1 + s * 8 + c + 4));
        }
    }

    auto issue = [&](int kt, int buf) {
        const float* kg = Kg + (size_t)kt * 4096;
        const float* vg = Vg + (size_t)kt * 4096;
#pragma unroll
        for (int j = 0; j < 4; j++) {
            int ci = tid + 256 * j;
            cp16(ksb + buf * 16384 + ci * 16, kg + ci * 4);
            cp16(vsb + buf * 16384 + ci * 16, vg + ci * 4);
        }
    };

    float oa[8][4];
#pragma unroll
    for (int nt = 0; nt < 8; nt++)
#pragma unroll
        for (int r = 0; r < 4; r++) oa[nt][r] = 0.f;
    float l0 = 0.f, l1 = 0.f;

    const int ktmax = 2 * qb + 1;
    issue(0, 0); CP_COMMIT();
    if (ktmax >= 1) issue(1, 1);
    CP_COMMIT();

    const int src0 = (lane & ~3) | (c >> 1);   // quad lane holding cols {c via reg c&1}
    const int src1 = src0 + 2;                 // quad lane holding cols {c+4 via reg c&1}
    const bool odd = (c & 1);

    for (int kt = 0; kt <= ktmax; kt++) {
        CP_WAIT(1);
        __syncthreads();
        if (kt + 2 <= ktmax) issue(kt + 2, (kt + 2) % 3);
        CP_COMMIT();

        const float* ks = Ksm + (kt % 3) * 4096;
        const float* vs = Vsm + (kt % 3) * 4096;
        const int pr0 = wid * 16 + g;
        const int row0 = qb * 128 + pr0;
        const bool clip = (kt >= 2 * qb);

        // ---- S = Q K^T (full 8-nt sweep) ----
        float sacc[8][4];
#pragma unroll
        for (int nt = 0; nt < 8; nt++)
#pragma unroll
            for (int r = 0; r < 4; r++) sacc[nt][r] = 0.f;
#pragma unroll
        for (int s = 0; s < 8; s++) {
#pragma unroll
            for (int nt = 0; nt < 8; nt++) {
                uint2 bv = *(const uint2*)&ks[swp64(nt * 8 + g, s * 8 + 2 * c)];
                mma8(sacc[nt], qf[s][0], qf[s][1], qf[s][2], qf[s][3], bv.x, bv.y);
            }
        }

        // ---- causal mask ----
        if (clip) {
#pragma unroll
            for (int nt = 0; nt < 8; nt++) {
                int col = kt * 64 + nt * 8 + 2 * c;
                if (col     > row0)     sacc[nt][0] = -INFINITY;
                if (col + 1 > row0)     sacc[nt][1] = -INFINITY;
                if (col     > row0 + 8) sacc[nt][2] = -INFINITY;
                if (col + 1 > row0 + 8) sacc[nt][3] = -INFINITY;
            }
        }

        // ---- direct exp2 + row sums + tf32 rounding in-register ----
#pragma unroll
        for (int nt = 0; nt < 8; nt++) {
            sacc[nt][0] = exp2f(sacc[nt][0]);
            sacc[nt][1] = exp2f(sacc[nt][1]);
            sacc[nt][2] = exp2f(sacc[nt][2]);
            sacc[nt][3] = exp2f(sacc[nt][3]);
            l0 += sacc[nt][0] + sacc[nt][1];
            l1 += sacc[nt][2] + sacc[nt][3];
            sacc[nt][0] = rtf(sacc[nt][0]);
            sacc[nt][1] = rtf(sacc[nt][1]);
            sacc[nt][2] = rtf(sacc[nt][2]);
            sacc[nt][3] = rtf(sacc[nt][3]);
        }

        // ---- O += P V, P fragments via quad-shuffle ----
#pragma unroll
        for (int s = 0; s < 8; s++) {
            float v00 = __shfl_sync(0xffffffffu, sacc[s][0], src0);
            float v01 = __shfl_sync(0xffffffffu, sacc[s][1], src0);
            float v02 = __shfl_sync(0xffffffffu, sacc[s][2], src0);
            float v03 = __shfl_sync(0xffffffffu, sacc[s][3], src0);
            float v10 = __shfl_sync(0xffffffffu, sacc[s][0], src1);
            float v11 = __shfl_sync(0xffffffffu, sacc[s][1], src1);
            float v12 = __shfl_sync(0xffffffffu, sacc[s][2], src1);
            float v13 = __shfl_sync(0xffffffffu, sacc[s][3], src1);
            unsigned a0 = __float_as_uint(odd ? v01 : v00);  // P[pr0][s*8+c]
            unsigned a1 = __float_as_uint(odd ? v03 : v02);  // P[pr0+8][s*8+c]
            unsigned a2 = __float_as_uint(odd ? v11 : v10);  // P[pr0][s*8+c+4]
            unsigned a3 = __float_as_uint(odd ? v13 : v12);  // P[pr0+8][s*8+c+4]
#pragma unroll
            for (int nt = 0; nt < 8; nt++) {
                uint2 bv = *(const uint2*)&vs[swp64(nt * 8 + g, s * 8 + 2 * c)];
                mma8(oa[nt], a0, a1, a2, a3, bv.x, bv.y);
            }
        }
    }

    // ---- epilogue: quad-reduce row sums, normalize, write packed ----
    l0 += __shfl_xor_sync(0xffffffffu, l0, 1);
    l0 += __shfl_xor_sync(0xffffffffu, l0, 2);
    l1 += __shfl_xor_sync(0xffffffffu, l1, 1);
    l1 += __shfl_xor_sync(0xffffffffu, l1, 2);
    float inv0 = 1.f / l0, inv1 = 1.f / l1;
    const int rr0 = wid * 16 + g;
    float* ob = Opk + ((size_t)(b * 32 + qb) * 32) * 4096;
#pragma unroll
    for (int nt = 0; nt < 8; nt++) {
        int cl = nt * 8 + 2 * c;
        int k = h * 64 + cl;
        float* blk = ob + (size_t)(k >> 5) * 4096;
        int kc = k & 31;
        blk[afrag_off(rr0,     kc)]     = rtf(oa[nt][0] * inv0);
        blk[afrag_off(rr0,     kc + 1)] = rtf(oa[nt][1] * inv0);
        blk[afrag_off(rr0 + 8, kc)]     = rtf(oa[nt][2] * inv1);
        blk[afrag_off(rr0 + 8, kc + 1)] = rtf(oa[nt][3] * inv1);
    }
}

// ---------------- launch ----------------
extern "C" void kernel_launch(void* const* d_in, const int* in_sizes, int n_in,
                              void* d_out, int out_size)
{
    const float* hs    = (const float*)d_in[0];
    const float* rcos  = (const float*)d_in[1];
    const float* rsin  = (const float*)d_in[2];
    const float* Wqkv  = (const float*)d_in[3];
    const float* Wo    = (const float*)d_in[4];
    const float* gq    = (const float*)d_in[5];
    const float* gk    = (const float*)d_in[6];
    float* out = (float*)d_out;

    float *qkv_p, *apk_p, *q_p, *kpk_p, *vpk_p, *opk_p, *wqkv_p, *wo_p;
    cudaGetSymbolAddress((void**)&qkv_p,  g_qkv);
    cudaGetSymbolAddress((void**)&apk_p,  g_apk);
    cudaGetSymbolAddress((void**)&q_p,    g_q);
    cudaGetSymbolAddress((void**)&kpk_p,  g_kpk);
    cudaGetSymbolAddress((void**)&vpk_p,  g_vpk);
    cudaGetSymbolAddress((void**)&opk_p,  g_opk);
    cudaGetSymbolAddress((void**)&wqkv_p, g_wqkv_pk);
    cudaGetSymbolAddress((void**)&wo_p,   g_wo_pk);

    const int GSMEM = GS * STW * (int)sizeof(float);          // 98304
    const int FSMEM = 24576 * (int)sizeof(float);             // 98304 (3-stage K+V)
    cudaFuncSetAttribute(gemm_mma,  cudaFuncAttributeMaxDynamicSharedMemorySize, GSMEM);
    cudaFuncSetAttribute(flash_mma, cudaFuncAttributeMaxDynamicSharedMemorySize, FSMEM);

    // prep: pack operands into fragment-order global layouts (tf32-rounded)
    pack_a<<<TOKENS * HID / 4 / 256, 256>>>(hs, apk_p, HID);
    pack_wT<<<dim3(QKVW / 32, HID / 32), dim3(32, 8)>>>(Wqkv, wqkv_p, HID, QKVW);
    pack_wT<<<dim3(HID / 32, HID / 32), dim3(32, 8)>>>(Wo, wo_p, HID, HID);

    // 1. QKV = hidden @ W_qkv   (128x128 tiles, 2 CTAs/SM)
    gemm_mma<<<dim3(QKVW / 128, TOKENS / 128), 256, GSMEM>>>(apk_p, wqkv_p, qkv_p,
                                                             TOKENS, QKVW, HID);
    // 2. RMSNorm + RoPE (q normal, k packed)
    rmsnorm_rope_kernel<<<TOKENS * NHEAD / 8, 256>>>(qkv_p, rcos, rsin, gq, gk, q_p, kpk_p);
    // 2b. V -> packed flash tiles
    pack_v<<<dim3(HDIM / 32, SEQ / 32, BATCH * NHEAD), dim3(32, 8)>>>(qkv_p, vpk_p);
    // 3. causal flash attention (LPT grid: x=bh, y=qb-descending)
    flash_mma<<<dim3(BATCH * NHEAD, SEQ / 128), 256, FSMEM>>>(q_p, kpk_p, vpk_p, opk_p);
    // 4. out = attn_out @ W_o
    gemm_mma<<<dim3(HID / 128, TOKENS / 128), 256, GSMEM>>>(opk_p, wo_p, out,
                                                            TOKENS, HID, HID);
}

// round 17
// speedup vs baseline: 1.1264x; 1.1264x over previous
#include <cuda_runtime.h>
#include <math.h>
#include <stdint.h>

// Problem constants: B=2, S=4096, H=1024, NH=16, hd=64
#define BATCH 2
#define SEQ   4096
#define HID   1024
#define NHEAD 16
#define HDIM  64
#define TOKENS (BATCH*SEQ)          // 8192
#define QKVW  (3*HID)               // 3072

// ---------------- device scratch ----------------
__device__ float g_qkv  [(size_t)TOKENS * QKVW];  // QKV gemm output, normal [t][3H]
__device__ float g_apk  [(size_t)TOKENS * HID];   // hidden, packed (A fragment order)
__device__ float g_q    [(size_t)TOKENS * HID];   // Q packed per 128x64 tile, fragment order
__device__ float g_kpk  [(size_t)TOKENS * HID];   // K packed for flash tiles (pk8 kv layout)
__device__ float g_vpk  [(size_t)TOKENS * HID];   // V packed for flash tiles (identity kv)
__device__ float g_opk  [(size_t)TOKENS * HID];   // attn out, packed (A fragment order)
__device__ float g_wqkv_pk[(size_t)QKVW * HID];   // W_qkv^T packed (B fragment order)
__device__ float g_wo_pk  [(size_t)HID * HID];    // W_o^T packed (B fragment order)

// ---------------- tf32 / layout helpers ----------------
__device__ __forceinline__ unsigned f2tf(float f) {
    unsigned u; asm("cvt.rna.tf32.f32 %0, %1;" : "=r"(u) : "f"(f)); return u;
}
__device__ __forceinline__ float rtf(float f) { return __uint_as_float(f2tf(f)); }

__device__ __forceinline__ void mma8(float (&c)[4],
                                     unsigned a0, unsigned a1, unsigned a2, unsigned a3,
                                     unsigned b0, unsigned b1) {
    asm volatile(
        "mma.sync.aligned.m16n8k8.row.col.f32.tf32.tf32.f32 "
        "{%0,%1,%2,%3},{%4,%5,%6,%7},{%8,%9},{%0,%1,%2,%3};\n"
        : "+f"(c[0]), "+f"(c[1]), "+f"(c[2]), "+f"(c[3])
        : "r"(a0), "r"(a1), "r"(a2), "r"(a3), "r"(b0), "r"(b1));
}

__device__ __forceinline__ unsigned smem_u32(const void* p) {
    unsigned a;
    asm("{ .reg .u64 t; cvta.to.shared.u64 t, %1; cvt.u32.u64 %0, t; }" : "=r"(a) : "l"(p));
    return a;
}
__device__ __forceinline__ void cp16(unsigned dst, const void* src) {
    asm volatile("cp.async.cg.shared.global [%0], [%1], 16;\n" :: "r"(dst), "l"(src) : "memory");
}
#define CP_COMMIT() asm volatile("cp.async.commit_group;\n" ::: "memory")
#define CP_WAIT(n)  asm volatile("cp.async.wait_group %0;\n" :: "n"(n) : "memory")

// k-permutation within 8-groups (K tiles only): kv (c, c+4) land at positions (2c, 2c+1)
__device__ __forceinline__ int pk8(int k) {
    return (k & ~7) | ((k & 3) << 1) | ((k >> 2) & 1);
}
// 64-float row xor swizzle (flash tiles)
__device__ __forceinline__ int swp64(int row, int p) {
    return row * 64 + ((((p >> 3) ^ (row & 7)) << 3) | (p & 7));
}

// ---- GEMM fragment-order offsets within a (128 rows x 32 k) = 4096-word tile ----
__device__ __forceinline__ int afrag_off(int r, int k) {   // r in [0,128), k in [0,32)
    int half = r >> 6, mt = (r >> 4) & 3, g = r & 7, hi = (r >> 3) & 1;
    int s = k >> 3, c2 = k & 3, h2 = (k >> 2) & 1;
    return ((half * 4 + mt) * 4 + s) * 128 + (g * 4 + c2) * 4 + h2 * 2 + hi;
}
__device__ __forceinline__ int bfrag_off(int n, int k) {   // n in [0,128), k in [0,32)
    int wq = n >> 5, nt = (n >> 3) & 3, g = n & 7;
    int s = k >> 3, c2 = k & 3, h2 = (k >> 2) & 1;
    return wq * 1024 + (nt * 4 + s) * 64 + (g * 4 + c2) * 2 + h2;
}
// Q fragment offset within a (128 rows x 64 hd) = 8192-word tile
__device__ __forceinline__ int qfrag_off(int r, int d) {   // r in [0,128), d in [0,64)
    int w = r >> 4, g = r & 7, hi = (r >> 3) & 1;
    return ((w * 8 + (d >> 3)) * 32 + (g * 4 + (d & 3))) * 4 + ((d >> 2) & 1) * 2 + hi;
}

// ---------------- prep kernels ----------------
__global__ void pack_a(const float* __restrict__ src, float* __restrict__ dst, int K) {
    int i = blockIdx.x * blockDim.x + threadIdx.x;
    int kq = K >> 2;
    int row = i / kq, k = (i - row * kq) * 4;
    float4 v = ((const float4*)src)[i];
    float* d = dst + ((size_t)(row >> 7) * (K >> 5) + (k >> 5)) * 4096;
    int r = row & 127, kc = k & 31;
    float vv[4] = {v.x, v.y, v.z, v.w};
#pragma unroll
    for (int e = 0; e < 4; e++)
        d[afrag_off(r, kc + e)] = rtf(vv[e]);
}

__global__ void pack_wT(const float* __restrict__ src, float* __restrict__ dst,
                        int K, int N) {
    __shared__ float t[32][33];
    int bn = blockIdx.x * 32, bk = blockIdx.y * 32;
    int x = threadIdx.x, y = threadIdx.y;
#pragma unroll
    for (int i = 0; i < 32; i += 8)
        t[y + i][x] = src[(size_t)(bk + y + i) * N + bn + x];
    __syncthreads();
#pragma unroll
    for (int i = 0; i < 32; i += 8) {
        int n = bn + y + i, k = bk + x;
        size_t blk = ((size_t)(n >> 7) * (K >> 5) + (k >> 5)) * 4096;
        dst[blk + bfrag_off(n & 127, k & 31)] = rtf(t[x][y + i]);
    }
}

// V slice of qkv -> flash tiles [bh][kvtile][hd row 64][kv 64], identity kv positions
__global__ void pack_v(const float* __restrict__ qkv, float* __restrict__ v) {
    __shared__ float t[32][33];
    int bh = blockIdx.z, b = bh >> 4, h = bh & 15;
    const float* src = qkv + (size_t)b * SEQ * QKVW + 2 * HID + h * HDIM;
    int bx = blockIdx.x * 32;   // hd tile
    int by = blockIdx.y * 32;   // s tile
    int x = threadIdx.x, y = threadIdx.y;
#pragma unroll
    for (int i = 0; i < 32; i += 8)
        t[y + i][x] = src[(size_t)(by + y + i) * QKVW + bx + x];
    __syncthreads();
#pragma unroll
    for (int i = 0; i < 32; i += 8) {
        int hd = bx + y + i, s = by + x;
        size_t blk = ((size_t)bh * (SEQ >> 6) + (s >> 6)) * 4096;
        v[blk + swp64(hd, s & 63)] = rtf(t[x][y + i]);
    }
}

// ---------------- RMSNorm + RoPE: q fragment-packed, k pk8-packed ----------------
__global__ void rmsnorm_rope_kernel(const float* __restrict__ qkv,
                                    const float* __restrict__ cosb,
                                    const float* __restrict__ sinb,
                                    const float* __restrict__ gq,
                                    const float* __restrict__ gk,
                                    float* __restrict__ qout,
                                    float* __restrict__ kout)
{
    int warp = (blockIdx.x * blockDim.x + threadIdx.x) >> 5;
    int lane = threadIdx.x & 31;
    if (warp >= TOKENS * NHEAD) return;
    int t = warp / NHEAD, h = warp % NHEAD;
    int s = t & (SEQ - 1), b = t / SEQ;
    int bh = b * NHEAD + h;

    const float* qp = qkv + (size_t)t * QKVW + h * HDIM;
    const float* kp = qp + HID;

    float q0 = qp[lane], q1 = qp[lane + 32];
    float k0 = kp[lane], k1 = kp[lane + 32];

    float sq = q0 * q0 + q1 * q1;
    float sk = k0 * k0 + k1 * k1;
#pragma unroll
    for (int off = 16; off; off >>= 1) {
        sq += __shfl_xor_sync(0xffffffffu, sq, off);
        sk += __shfl_xor_sync(0xffffffffu, sk, off);
    }
    float rq = rsqrtf(sq * (1.0f / HDIM) + 1e-6f);
    float rk = rsqrtf(sk * (1.0f / HDIM) + 1e-6f);
    q0 *= rq * gq[lane];  q1 *= rq * gq[lane + 32];
    k0 *= rk * gk[lane];  k1 *= rk * gk[lane + 32];

    float c0 = cosb[(size_t)s * HDIM + lane];
    float c1 = cosb[(size_t)s * HDIM + lane + 32];
    float s0 = sinb[(size_t)s * HDIM + lane];
    float s1 = sinb[(size_t)s * HDIM + lane + 32];

    float qv0 = rtf(q0 * c0 - q1 * s0);
    float qv1 = rtf(q1 * c1 + q0 * s1);

    // q: fragment-packed per (bh, qtile) 128x64 tile
    int qbt = s >> 7, r = s & 127;
    size_t qbase = ((size_t)bh * (SEQ >> 7) + qbt) * 8192;
    qout[qbase + qfrag_off(r, lane)]      = qv0;
    qout[qbase + qfrag_off(r, lane + 32)] = qv1;

    // k: pk8 kv layout (positions (2c,2c+1) hold kv (c,c+4))
    size_t kblk = ((size_t)bh * (SEQ >> 6) + (s >> 6)) * 4096;
    int kr = s & 63;
    kout[kblk + swp64(kr, pk8(lane))]      = rtf(k0 * c0 - k1 * s0);
    kout[kblk + swp64(kr, pk8(lane + 32))] = rtf(k1 * c1 + k0 * s1);
}

// ============ tf32 HMMA GEMM, fragment-order operands: C = A @ B^T, 128x128x32 ============
#define GS 3
#define STW 8192   // words per stage (A 4096 + B 4096)
__global__ __launch_bounds__(256, 2)
void gemm_mma(const float* __restrict__ Apk, const float* __restrict__ Bpk,
              float* __restrict__ C, int M, int N, int K)
{
    extern __shared__ float smf[];
    const int tid = threadIdx.x, lane = tid & 31, wid = tid >> 5;
    const int g = lane >> 2, c = lane & 3;
    const int half = wid >> 2, wq = wid & 3;
    const size_t bm = (size_t)blockIdx.y * 128, bn = (size_t)blockIdx.x * 128;
    const int NK = K >> 5;
    const float* ag = Apk + (size_t)blockIdx.y * NK * 4096;
    const float* bg = Bpk + (size_t)blockIdx.x * NK * 4096;
    const unsigned sb = smem_u32(smf);

    auto issue = [&](int kt, int st) {
        const float* a = ag + (size_t)kt * 4096;
        const float* b = bg + (size_t)kt * 4096;
        const unsigned d = sb + st * (STW * 4);
#pragma unroll
        for (int j = 0; j < 4; j++) {
            int ci = tid + 256 * j;
            cp16(d + ci * 16, a + ci * 4);
            cp16(d + 16384 + ci * 16, b + ci * 4);
        }
    };

    float acc[4][4][4];
#pragma unroll
    for (int i = 0; i < 4; i++)
#pragma unroll
        for (int j = 0; j < 4; j++)
#pragma unroll
            for (int r = 0; r < 4; r++) acc[i][j][r] = 0.f;

    issue(0, 0); CP_COMMIT();
    issue(1, 1); CP_COMMIT();

    for (int kt = 0; kt < NK; kt++) {
        CP_WAIT(1);
        __syncthreads();
        if (kt + 2 < NK) issue(kt + 2, (kt + 2) % 3);
        CP_COMMIT();

        const float* as = smf + (kt % 3) * STW + half * 2048 + lane * 4;
        const float* bs = smf + (kt % 3) * STW + 4096 + wq * 1024 + lane * 2;
#pragma unroll
        for (int s = 0; s < 4; s++) {
            uint4 a4[4];
            uint2 bv[4];
#pragma unroll
            for (int mt = 0; mt < 4; mt++)
                a4[mt] = *(const uint4*)&as[(mt * 4 + s) * 128];
#pragma unroll
            for (int nt = 0; nt < 4; nt++)
                bv[nt] = *(const uint2*)&bs[(nt * 4 + s) * 64];
#pragma unroll
            for (int mt = 0; mt < 4; mt++)
#pragma unroll
                for (int nt = 0; nt < 4; nt++)
                    mma8(acc[mt][nt], a4[mt].x, a4[mt].y, a4[mt].z, a4[mt].w,
                         bv[nt].x, bv[nt].y);
        }
    }

    const int wm = half * 64, wn = wq * 32;
#pragma unroll
    for (int mt = 0; mt < 4; mt++) {
        size_t row = bm + wm + mt * 16 + g;
#pragma unroll
        for (int nt = 0; nt < 4; nt++) {
            size_t col = bn + wn + nt * 8 + 2 * c;
            *(float2*)(C + row * N + col)       = make_float2(acc[mt][nt][0], acc[mt][nt][1]);
            *(float2*)(C + (row + 8) * N + col) = make_float2(acc[mt][nt][2], acc[mt][nt][3]);
        }
    }
}

// ---------------- causal flash attention, no-max softmax, 2 CTAs/SM ----------------
// P/V use identity kv positions: P stores are STS.64 pairs (sacc holds kv 2c,2c+1),
// PV loads read positions (2c,2c+1) for both P and V -- mutually consistent k-slots.
// smem words: K 2x4096 | V 2x4096 | P 8192 = 24576 (96KB); 2 CTAs/SM = 192KB.
__global__ __launch_bounds__(256, 2)
void flash_mma(const float* __restrict__ Q, const float* __restrict__ Kpk,
               const float* __restrict__ Vpk, float* __restrict__ Opk)
{
    extern __shared__ float sm[];
    float* Ksm = sm;            // [2][64*64]
    float* Vsm = sm + 8192;     // [2][64*64]
    float* Ps  = sm + 16384;    // [128*64]

    const int tid = threadIdx.x, lane = tid & 31, wid = tid >> 5;
    const int g = lane >> 2, c = lane & 3;
    const int qb = (SEQ / 128 - 1) - blockIdx.y;   // LPT: largest work first
    const int bh = blockIdx.x;
    const int b = bh >> 4, h = bh & 15;

    const float* Kg = Kpk + (size_t)bh * (SEQ >> 6) * 4096;
    const float* Vg = Vpk + (size_t)bh * (SEQ >> 6) * 4096;
    const unsigned ksb = smem_u32(Ksm), vsb = smem_u32(Vsm);

    // persistent Q fragments: coalesced LDG.128 from fragment-packed tile, scaled
    const float QS = 0.18033688f;   // 0.125 * log2(e)
    unsigned qf[8][4];
    {
        const float4* qg = (const float4*)(Q + ((size_t)bh * (SEQ >> 7) + qb) * 8192)
                         + (size_t)wid * 8 * 32 + lane;
#pragma unroll
        for (int s = 0; s < 8; s++) {
            float4 v = __ldg(qg + s * 32);
            qf[s][0] = f2tf(QS * v.x);
            qf[s][1] = f2tf(QS * v.y);
            qf[s][2] = f2tf(QS * v.z);
            qf[s][3] = f2tf(QS * v.w);
        }
    }

    auto issue = [&](int kt, int buf) {
        const float* kg = Kg + (size_t)kt * 4096;
        const float* vg = Vg + (size_t)kt * 4096;
#pragma unroll
        for (int j = 0; j < 4; j++) {
            int ci = tid + 256 * j;
            cp16(ksb + buf * 16384 + ci * 16, kg + ci * 4);
            cp16(vsb + buf * 16384 + ci * 16, vg + ci * 4);
        }
    };

    float oa[8][4];
#pragma unroll
    for (int nt = 0; nt < 8; nt++)
#pragma unroll
        for (int r = 0; r < 4; r++) oa[nt][r] = 0.f;
    float l0 = 0.f, l1 = 0.f;

    const int ktmax = 2 * qb + 1;
    issue(0, 0); CP_COMMIT();

    for (int kt = 0; kt <= ktmax; kt++) {
        CP_WAIT(0);
        __syncthreads();
        if (kt < ktmax) issue(kt + 1, (kt + 1) & 1);
        CP_COMMIT();

        const float* ks = Ksm + (kt & 1) * 4096;
        const float* vs = Vsm + (kt & 1) * 4096;
        const int pr0 = wid * 16 + g, pr1 = pr0 + 8;
        const int row0 = qb * 128 + pr0;
        const bool clip = (kt >= 2 * qb);

        // ---- S = Q K^T in two nt-halves (keeps sacc at 16 regs) ----
#pragma unroll
        for (int hf = 0; hf < 2; hf++) {
            float sacc[4][4];
#pragma unroll
            for (int nt = 0; nt < 4; nt++)
#pragma unroll
                for (int r = 0; r < 4; r++) sacc[nt][r] = 0.f;
#pragma unroll
            for (int s = 0; s < 8; s++) {
#pragma unroll
                for (int nt = 0; nt < 4; nt++) {
                    uint2 bv = *(const uint2*)&ks[swp64((hf * 4 + nt) * 8 + g, s * 8 + 2 * c)];
                    mma8(sacc[nt], qf[s][0], qf[s][1], qf[s][2], qf[s][3], bv.x, bv.y);
                }
            }

            if (clip) {
#pragma unroll
                for (int nt = 0; nt < 4; nt++) {
                    int col = kt * 64 + (hf * 4 + nt) * 8 + 2 * c;
                    if (col     > row0)     sacc[nt][0] = -INFINITY;
                    if (col + 1 > row0)     sacc[nt][1] = -INFINITY;
                    if (col     > row0 + 8) sacc[nt][2] = -INFINITY;
                    if (col + 1 > row0 + 8) sacc[nt][3] = -INFINITY;
                }
            }

#pragma unroll
            for (int nt = 0; nt < 4; nt++) {
                sacc[nt][0] = exp2f(sacc[nt][0]);
                sacc[nt][1] = exp2f(sacc[nt][1]);
                sacc[nt][2] = exp2f(sacc[nt][2]);
                sacc[nt][3] = exp2f(sacc[nt][3]);
                l0 += sacc[nt][0] + sacc[nt][1];
                l1 += sacc[nt][2] + sacc[nt][3];
            }

            // P -> smem: identity kv positions => vectorized STS.64 pairs
#pragma unroll
            for (int nt = 0; nt < 4; nt++) {
                int cl = (hf * 4 + nt) * 8 + 2 * c;
                *(float2*)&Ps[swp64(pr0, cl)] =
                    make_float2(__uint_as_float(f2tf(sacc[nt][0])),
                                __uint_as_float(f2tf(sacc[nt][1])));
                *(float2*)&Ps[swp64(pr1, cl)] =
                    make_float2(__uint_as_float(f2tf(sacc[nt][2])),
                                __uint_as_float(f2tf(sacc[nt][3])));
            }
        }
        __syncwarp();

        // ---- O += P V (P and V both at identity kv positions) ----
#pragma unroll
        for (int s = 0; s < 8; s++) {
            uint2 lo = *(const uint2*)&Ps[swp64(pr0, s * 8 + 2 * c)];
            uint2 hi = *(const uint2*)&Ps[swp64(pr1, s * 8 + 2 * c)];
#pragma unroll
            for (int nt = 0; nt < 8; nt++) {
                uint2 bv = *(const uint2*)&vs[swp64(nt * 8 + g, s * 8 + 2 * c)];
                mma8(oa[nt], lo.x, hi.x, lo.y, hi.y, bv.x, bv.y);
            }
        }
    }

    // ---- epilogue: quad-reduce row sums, normalize, write packed ----
    l0 += __shfl_xor_sync(0xffffffffu, l0, 1);
    l0 += __shfl_xor_sync(0xffffffffu, l0, 2);
    l1 += __shfl_xor_sync(0xffffffffu, l1, 1);
    l1 += __shfl_xor_sync(0xffffffffu, l1, 2);
    float inv0 = 1.f / l0, inv1 = 1.f / l1;
    const int rr0 = wid * 16 + g;
    float* ob = Opk + ((size_t)(b * 32 + qb) * 32) * 4096;
#pragma unroll
    for (int nt = 0; nt < 8; nt++) {
        int cl = nt * 8 + 2 * c;
        int k = h * 64 + cl;
        float* blk = ob + (size_t)(k >> 5) * 4096;
        int kc = k & 31;
        blk[afrag_off(rr0,     kc)]     = rtf(oa[nt][0] * inv0);
        blk[afrag_off(rr0,     kc + 1)] = rtf(oa[nt][1] * inv0);
        blk[afrag_off(rr0 + 8, kc)]     = rtf(oa[nt][2] * inv1);
        blk[afrag_off(rr0 + 8, kc + 1)] = rtf(oa[nt][3] * inv1);
    }
}

// ---------------- launch ----------------
extern "C" void kernel_launch(void* const* d_in, const int* in_sizes, int n_in,
                              void* d_out, int out_size)
{
    const float* hs    = (const float*)d_in[0];
    const float* rcos  = (const float*)d_in[1];
    const float* rsin  = (const float*)d_in[2];
    const float* Wqkv  = (const float*)d_in[3];
    const float* Wo    = (const float*)d_in[4];
    const float* gq    = (const float*)d_in[5];
    const float* gk    = (const float*)d_in[6];
    float* out = (float*)d_out;

    float *qkv_p, *apk_p, *q_p, *kpk_p, *vpk_p, *opk_p, *wqkv_p, *wo_p;
    cudaGetSymbolAddress((void**)&qkv_p,  g_qkv);
    cudaGetSymbolAddress((void**)&apk_p,  g_apk);
    cudaGetSymbolAddress((void**)&q_p,    g_q);
    cudaGetSymbolAddress((void**)&kpk_p,  g_kpk);
    cudaGetSymbolAddress((void**)&vpk_p,  g_vpk);
    cudaGetSymbolAddress((void**)&opk_p,  g_opk);
    cudaGetSymbolAddress((void**)&wqkv_p, g_wqkv_pk);
    cudaGetSymbolAddress((void**)&wo_p,   g_wo_pk);

    const int GSMEM = GS * STW * (int)sizeof(float);          // 98304
    const int FSMEM = 24576 * (int)sizeof(float);             // 98304
    cudaFuncSetAttribute(gemm_mma,  cudaFuncAttributeMaxDynamicSharedMemorySize, GSMEM);
    cudaFuncSetAttribute(flash_mma, cudaFuncAttributeMaxDynamicSharedMemorySize, FSMEM);

    // prep: pack operands into fragment-order global layouts (tf32-rounded)
    pack_a<<<TOKENS * HID / 4 / 256, 256>>>(hs, apk_p, HID);
    pack_wT<<<dim3(QKVW / 32, HID / 32), dim3(32, 8)>>>(Wqkv, wqkv_p, HID, QKVW);
    pack_wT<<<dim3(HID / 32, HID / 32), dim3(32, 8)>>>(Wo, wo_p, HID, HID);

    // 1. QKV = hidden @ W_qkv   (128x128 tiles, 2 CTAs/SM)
    gemm_mma<<<dim3(QKVW / 128, TOKENS / 128), 256, GSMEM>>>(apk_p, wqkv_p, qkv_p,
                                                             TOKENS, QKVW, HID);
    // 2. RMSNorm + RoPE (q fragment-packed, k pk8-packed)
    rmsnorm_rope_kernel<<<TOKENS * NHEAD / 8, 256>>>(qkv_p, rcos, rsin, gq, gk, q_p, kpk_p);
    // 2b. V -> flash tiles (identity kv)
    pack_v<<<dim3(HDIM / 32, SEQ / 32, BATCH * NHEAD), dim3(32, 8)>>>(qkv_p, vpk_p);
    // 3. causal flash attention (LPT grid: x=bh, y=qb-descending)
    flash_mma<<<dim3(BATCH * NHEAD, SEQ / 128), 256, FSMEM>>>(q_p, kpk_p, vpk_p, opk_p);
    // 4. out = attn_out @ W_o
    gemm_mma<<<dim3(HID / 128, TOKENS / 128), 256, GSMEM>>>(opk_p, wo_p, out,
                                                            TOKENS, HID, HID);
}